// round 8
// baseline (speedup 1.0000x reference)
#include <cuda_runtime.h>
#include <math.h>

#define BB    2
#define HH    360
#define WG    360
#define HW    (HH*WG)          // 129600
#define NCLS  10
#define NPROP 200
#define CC    128
#define NPTS  80000
#define NBUCK 8192             // bucket = float_bits >> 17
#define SEL_CAP 4096

// output layout: qf (B,C,P) | query_pos (B,P,2) | qhs (B,NCLS,P) | cls (B,P)
#define OFF_QF  0
#define OFF_POS (BB*CC*NPROP)            // 51200
#define OFF_QHS (OFF_POS + BB*NPROP*2)   // 52000
#define OFF_CLS (OFF_QHS + BB*NCLS*NPROP)// 56000

typedef unsigned long long ull;

// ---------------- scratch ---------------------------------------------------
__device__ float g_heat8[BB*HW*8];       // packed: [b*HW+cell][c], classes 0..7
__device__ float g_supp_pt[NPTS*NCLS];   // per-point suppressed heat, all 10 cls
__device__ int   g_map[BB*HW];           // cell -> row; only written cells read
__device__ unsigned g_hist[BB*NBUCK];
__device__ int   g_thr[BB];
__device__ int   g_selcnt[BB];
__device__ ull   g_sel[BB*SEL_CAP];

// ---------------- packed f32x2 helpers --------------------------------------
__device__ __forceinline__ ull pk2(float lo, float hi) {
    ull r;
    asm("mov.b64 %0, {%1, %2};" : "=l"(r)
        : "r"(__float_as_uint(lo)), "r"(__float_as_uint(hi)));
    return r;
}
__device__ __forceinline__ ull pk1(float v) {
    ull r;
    asm("mov.b64 %0, {%1, %1};" : "=l"(r) : "r"(__float_as_uint(v)));
    return r;
}
__device__ __forceinline__ void upk(ull p, float& lo, float& hi) {
    unsigned a, b;
    asm("mov.b64 {%0, %1}, %2;" : "=r"(a), "=r"(b) : "l"(p));
    lo = __uint_as_float(a); hi = __uint_as_float(b);
}
__device__ __forceinline__ ull ffma2(ull a, ull b, ull c) {
    ull d;
    asm("fma.rn.f32x2 %0, %1, %2, %3;" : "=l"(d) : "l"(a), "l"(b), "l"(c));
    return d;
}
__device__ __forceinline__ float sigmf(float x) {
    return 1.f / (1.f + expf(-x));
}

// ---------------- init ------------------------------------------------------
__global__ void init_kernel() {
    int stride = gridDim.x * blockDim.x;
    int i0 = blockIdx.x * blockDim.x + threadIdx.x;
    float4 z = make_float4(0.f, 0.f, 0.f, 0.f);
    for (int j = i0; j < BB*HW*8/4; j += stride) ((float4*)g_heat8)[j] = z;
    uint4 zu = make_uint4(0u, 0u, 0u, 0u);
    for (int j = i0; j < BB*NBUCK/4; j += stride) ((uint4*)g_hist)[j] = zu;
    if (i0 < BB) g_selcnt[i0] = 0;
}

// ---------------- fused MLP head (persistent, balanced tiles) ---------------
// grid = 296 (2 blocks/SM). Each block: 4 tiles of 64 rows (296*4*64 = 75776)
// then blocks 0..263 do one 16-row tail tile (264*16 = 4224). Total 80000.
// smem (floats): sW1 [0,16384) | sA2(ull pairs) overlays [16384,20608) |
//                sH [16384,24832) | sW2 [24832,26112)
#define GEMM_GRID 296
#define SMEM_FLOATS 26112
__global__ void __launch_bounds__(256, 2)
gemm_kernel(const float* __restrict__ feat, const float* __restrict__ W1,
            const float* __restrict__ b1,  const float* __restrict__ W2,
            const float* __restrict__ b2,  const int* __restrict__ idxs)
{
    extern __shared__ float sm[];
    float* sW1 = sm;                        // 128*128
    ull*   sA2 = (ull*)(sm + 16384);        // 32 k * 66 ull (dup pairs)
    float* sH  = sm + 16384;                // 64*132 (overlays sA2)
    float* sW2 = sm + 24832;                // 128*10

    const int tid = threadIdx.x;
    for (int i = tid*4; i < CC*CC; i += 256*4)
        *(float4*)(sW1 + i) = *(const float4*)(W1 + i);
    for (int i = tid; i < CC*NCLS; i += 256)
        sW2[i] = W2[i];

    const int tn = tid & 15, tm = tid >> 4;
    const int c0 = tn*4, c1 = 64 + tn*4;
    const ull bp0 = pk2(b1[c0],   b1[c0+1]);
    const ull bp1 = pk2(b1[c0+2], b1[c0+3]);
    const ull bp2 = pk2(b1[c1],   b1[c1+1]);
    const ull bp3 = pk2(b1[c1+2], b1[c1+3]);
    __syncthreads();

    // ---- main: 4 x 64-row tiles per block ----
    const int lr = tid >> 2;           // 0..63 (A-load row)
    const int lk = (tid & 3) * 4;      // 0,4,8,12 (A-load k quad)
    for (int tt = 0; tt < 4; tt++) {
        const int rowB = (blockIdx.x + tt*GEMM_GRID) * 64;
        ull acc[4][4];
#pragma unroll
        for (int i = 0; i < 4; i++) {
            acc[i][0] = bp0; acc[i][1] = bp1; acc[i][2] = bp2; acc[i][3] = bp3;
        }
        for (int kc = 0; kc < 4; kc++) {
            const float* fp = feat + (size_t)(rowB + lr)*CC + kc*32;
            float4 v0 = *(const float4*)(fp + lk);
            float4 v1 = *(const float4*)(fp + 16 + lk);
            sA2[(lk+0)*66 + lr] = pk1(v0.x);
            sA2[(lk+1)*66 + lr] = pk1(v0.y);
            sA2[(lk+2)*66 + lr] = pk1(v0.z);
            sA2[(lk+3)*66 + lr] = pk1(v0.w);
            sA2[(16+lk+0)*66 + lr] = pk1(v1.x);
            sA2[(16+lk+1)*66 + lr] = pk1(v1.y);
            sA2[(16+lk+2)*66 + lr] = pk1(v1.z);
            sA2[(16+lk+3)*66 + lr] = pk1(v1.w);
            __syncthreads();
#pragma unroll 2
            for (int k = 0; k < 32; k++) {
                const ull* ap = sA2 + k*66 + tm*4;
                ull a0 = ap[0], a1 = ap[1], a2 = ap[2], a3 = ap[3];
                const ull* bw = (const ull*)(sW1 + (kc*32+k)*CC);
                ull w0 = bw[tn*2], w1 = bw[tn*2+1];
                ull w2 = bw[32+tn*2], w3 = bw[32+tn*2+1];
                acc[0][0]=ffma2(a0,w0,acc[0][0]); acc[0][1]=ffma2(a0,w1,acc[0][1]);
                acc[0][2]=ffma2(a0,w2,acc[0][2]); acc[0][3]=ffma2(a0,w3,acc[0][3]);
                acc[1][0]=ffma2(a1,w0,acc[1][0]); acc[1][1]=ffma2(a1,w1,acc[1][1]);
                acc[1][2]=ffma2(a1,w2,acc[1][2]); acc[1][3]=ffma2(a1,w3,acc[1][3]);
                acc[2][0]=ffma2(a2,w0,acc[2][0]); acc[2][1]=ffma2(a2,w1,acc[2][1]);
                acc[2][2]=ffma2(a2,w2,acc[2][2]); acc[2][3]=ffma2(a2,w3,acc[2][3]);
                acc[3][0]=ffma2(a3,w0,acc[3][0]); acc[3][1]=ffma2(a3,w1,acc[3][1]);
                acc[3][2]=ffma2(a3,w2,acc[3][2]); acc[3][3]=ffma2(a3,w3,acc[3][3]);
            }
            __syncthreads();
        }
        // relu -> sH
#pragma unroll
        for (int i = 0; i < 4; i++) {
            int r = tm*4 + i;
            float lo, hi;
            upk(acc[i][0], lo, hi);
            *(ull*)(sH + r*132 + c0)     = pk2(fmaxf(lo,0.f), fmaxf(hi,0.f));
            upk(acc[i][1], lo, hi);
            *(ull*)(sH + r*132 + c0 + 2) = pk2(fmaxf(lo,0.f), fmaxf(hi,0.f));
            upk(acc[i][2], lo, hi);
            *(ull*)(sH + r*132 + c1)     = pk2(fmaxf(lo,0.f), fmaxf(hi,0.f));
            upk(acc[i][3], lo, hi);
            *(ull*)(sH + r*132 + c1 + 2) = pk2(fmaxf(lo,0.f), fmaxf(hi,0.f));
        }
        __syncthreads();
        // phase 2: hm = H@W2 + b2, sigmoid, scatter (128 threads)
        if (tid < 128) {
            int r = tid & 63, grp = tid >> 6;
            float o[5];
#pragma unroll
            for (int i = 0; i < 5; i++) o[i] = b2[grp*5 + i];
            for (int j = 0; j < 128; j++) {
                float a = sH[r*132 + j];
#pragma unroll
                for (int i = 0; i < 5; i++)
                    o[i] = fmaf(a, sW2[j*NCLS + grp*5 + i], o[i]);
            }
            int gr = rowB + r;
            int bi = idxs[gr*3], yi = idxs[gr*3+1], xi = idxs[gr*3+2];
            int cell = bi*HW + yi*WG + xi;
            if (grp == 0) {
#pragma unroll
                for (int i = 0; i < 5; i++)
                    g_heat8[(size_t)cell*8 + i] = sigmf(o[i]);
                g_map[cell] = gr;
            } else {
#pragma unroll
                for (int i = 0; i < 3; i++)
                    g_heat8[(size_t)cell*8 + 5 + i] = sigmf(o[i]);
#pragma unroll
                for (int i = 3; i < 5; i++) {     // classes 8,9: NMS bypass
                    float s = sigmf(o[i]);
                    g_supp_pt[gr*NCLS + 5 + i] = s;
                    atomicAdd(&g_hist[bi*NBUCK + (__float_as_uint(s) >> 17)], 1u);
                }
            }
        }
        __syncthreads();
    }

    // ---- tail: 264 x 16-row tiles, 1 per block ----
    if (blockIdx.x < 264) {
        const int rowB = 75776 + blockIdx.x * 16;
        ull acc[4];
        acc[0] = bp0; acc[1] = bp1; acc[2] = bp2; acc[3] = bp3;
        for (int kc = 0; kc < 4; kc++) {
            if (tid < 128) {
                int r  = tid >> 3;          // 0..15
                int k4 = (tid & 7) * 4;     // 0..28
                const float* fp = feat + (size_t)(rowB + r)*CC + kc*32 + k4;
                float4 v = *(const float4*)fp;
                sA2[(k4+0)*66 + r] = pk1(v.x);
                sA2[(k4+1)*66 + r] = pk1(v.y);
                sA2[(k4+2)*66 + r] = pk1(v.z);
                sA2[(k4+3)*66 + r] = pk1(v.w);
            }
            __syncthreads();
#pragma unroll 2
            for (int k = 0; k < 32; k++) {
                ull a = sA2[k*66 + tm];
                const ull* bw = (const ull*)(sW1 + (kc*32+k)*CC);
                ull w0 = bw[tn*2], w1 = bw[tn*2+1];
                ull w2 = bw[32+tn*2], w3 = bw[32+tn*2+1];
                acc[0] = ffma2(a, w0, acc[0]);
                acc[1] = ffma2(a, w1, acc[1]);
                acc[2] = ffma2(a, w2, acc[2]);
                acc[3] = ffma2(a, w3, acc[3]);
            }
            __syncthreads();
        }
        {
            int r = tm;
            float lo, hi;
            upk(acc[0], lo, hi);
            *(ull*)(sH + r*132 + c0)     = pk2(fmaxf(lo,0.f), fmaxf(hi,0.f));
            upk(acc[1], lo, hi);
            *(ull*)(sH + r*132 + c0 + 2) = pk2(fmaxf(lo,0.f), fmaxf(hi,0.f));
            upk(acc[2], lo, hi);
            *(ull*)(sH + r*132 + c1)     = pk2(fmaxf(lo,0.f), fmaxf(hi,0.f));
            upk(acc[3], lo, hi);
            *(ull*)(sH + r*132 + c1 + 2) = pk2(fmaxf(lo,0.f), fmaxf(hi,0.f));
        }
        __syncthreads();
        if (tid < 32) {
            int r = tid & 15, grp = tid >> 4;
            float o[5];
#pragma unroll
            for (int i = 0; i < 5; i++) o[i] = b2[grp*5 + i];
            for (int j = 0; j < 128; j++) {
                float a = sH[r*132 + j];
#pragma unroll
                for (int i = 0; i < 5; i++)
                    o[i] = fmaf(a, sW2[j*NCLS + grp*5 + i], o[i]);
            }
            int gr = rowB + r;
            int bi = idxs[gr*3], yi = idxs[gr*3+1], xi = idxs[gr*3+2];
            int cell = bi*HW + yi*WG + xi;
            if (grp == 0) {
#pragma unroll
                for (int i = 0; i < 5; i++)
                    g_heat8[(size_t)cell*8 + i] = sigmf(o[i]);
                g_map[cell] = gr;
            } else {
#pragma unroll
                for (int i = 0; i < 3; i++)
                    g_heat8[(size_t)cell*8 + 5 + i] = sigmf(o[i]);
#pragma unroll
                for (int i = 3; i < 5; i++) {
                    float s = sigmf(o[i]);
                    g_supp_pt[gr*NCLS + 5 + i] = s;
                    atomicAdd(&g_hist[bi*NBUCK + (__float_as_uint(s) >> 17)], 1u);
                }
            }
        }
    }
}

// ---------------- NMS per point (packed heat, classes 0..7) -----------------
__global__ void nms_kernel(const int* __restrict__ idxs) {
    int t = blockIdx.x * 256 + threadIdx.x;
    if (t >= NPTS) return;
    int b = idxs[3*t], y = idxs[3*t+1], x = idxs[3*t+2];
    int cell = b*HW + y*WG + x;
    float s[8];
    if (y > 0 && y < HH-1 && x > 0 && x < WG-1) {
        const float4* cp = (const float4*)(g_heat8 + (size_t)cell*8);
        float4 cv0 = cp[0], cv1 = cp[1];
        float ctr[8] = {cv0.x, cv0.y, cv0.z, cv0.w, cv1.x, cv1.y, cv1.z, cv1.w};
        float nmx[8] = {0.f,0.f,0.f,0.f,0.f,0.f,0.f,0.f};
        const int offs[8] = {-WG-1, -WG, -WG+1, -1, 1, WG-1, WG, WG+1};
#pragma unroll
        for (int n = 0; n < 8; n++) {
            const float4* q = (const float4*)(g_heat8 + (size_t)(cell + offs[n])*8);
            float4 u0 = q[0], u1 = q[1];
            nmx[0] = fmaxf(nmx[0], u0.x); nmx[1] = fmaxf(nmx[1], u0.y);
            nmx[2] = fmaxf(nmx[2], u0.z); nmx[3] = fmaxf(nmx[3], u0.w);
            nmx[4] = fmaxf(nmx[4], u1.x); nmx[5] = fmaxf(nmx[5], u1.y);
            nmx[6] = fmaxf(nmx[6], u1.z); nmx[7] = fmaxf(nmx[7], u1.w);
        }
#pragma unroll
        for (int c = 0; c < 8; c++)
            s[c] = (ctr[c] >= nmx[c]) ? ctr[c] : 0.f;
    } else {
#pragma unroll
        for (int c = 0; c < 8; c++) s[c] = 0.f;   // border suppressed (cls 0..7)
    }
#pragma unroll
    for (int c = 0; c < 8; c++) {
        g_supp_pt[t*NCLS + c] = s[c];
        if (s[c] > 0.f)
            atomicAdd(&g_hist[b*NBUCK + (__float_as_uint(s[c]) >> 17)], 1u);
    }
}

// ---------------- threshold bucket of rank-200 (warp-shuffle suffix scan) ---
__global__ void thresh_kernel() {
    __shared__ unsigned wtot[32], wexc[32];
    int b = blockIdx.x;
    const unsigned* h = g_hist + b*NBUCK;
    int t = threadIdx.x;
    uint4 h0 = ((const uint4*)h)[t*2];
    uint4 h1 = ((const uint4*)h)[t*2 + 1];
    unsigned hv[8] = {h0.x, h0.y, h0.z, h0.w, h1.x, h1.y, h1.z, h1.w};
    unsigned v = hv[0]+hv[1]+hv[2]+hv[3]+hv[4]+hv[5]+hv[6]+hv[7];

    int lane = t & 31, wid = t >> 5;
    unsigned s = v;                              // inclusive lane-suffix
#pragma unroll
    for (int off = 1; off < 32; off <<= 1) {
        unsigned u = __shfl_down_sync(0xFFFFFFFFu, s, off);
        if (lane + off < 32) s += u;
    }
    if (lane == 0) wtot[wid] = s;
    __syncthreads();
    if (wid == 0) {
        unsigned ws = wtot[lane];
        unsigned sw = ws;
#pragma unroll
        for (int off = 1; off < 32; off <<= 1) {
            unsigned u = __shfl_down_sync(0xFFFFFFFFu, sw, off);
            if (lane + off < 32) sw += u;
        }
        wexc[lane] = sw - ws;                    // strict suffix of warp totals
    }
    __syncthreads();
    unsigned S = s + wexc[wid];                  // suffix over all t' >= t
    unsigned Snext = S - v;
    if (S >= NPROP && Snext < NPROP) {
        unsigned acc = Snext;
        int T = t*8;
        for (int i = 7; i >= 0; i--) {
            if (acc + hv[i] >= NPROP) { T = t*8 + i; break; }
            acc += hv[i];
        }
        g_thr[b] = T;
    }
}

// ---------------- gather candidates >= threshold (per point) ----------------
__global__ void gather_kernel(const int* __restrict__ idxs) {
    int t = blockIdx.x * 256 + threadIdx.x;
    if (t >= NPTS) return;
    int b = idxs[3*t], y = idxs[3*t+1], x = idxs[3*t+2];
    int cell = y*WG + x;
    int T = g_thr[b];
#pragma unroll
    for (int c = 0; c < NCLS; c++) {
        float sv = g_supp_pt[t*NCLS + c];
        unsigned vb = __float_as_uint(sv);
        if (sv > 0.f && (int)(vb >> 17) >= T) {
            unsigned j = (unsigned)(c*HW + cell);
            ull sk = ((ull)vb << 32) | (ull)(0xFFFFFFFFu - j);
            int p = atomicAdd(&g_selcnt[b], 1);
            if (p < SEL_CAP) g_sel[b*SEL_CAP + p] = sk;
        }
    }
}

// ---------------- finalize: exact rank + all outputs (1 block / batch) ------
__global__ void finalize_kernel(const float* __restrict__ feat,
                                const float* __restrict__ Wcls,
                                const float* __restrict__ bcls,
                                float* __restrict__ out)
{
    __shared__ ull ssk[SEL_CAP];
    __shared__ ull stop[NPROP];
    int b = blockIdx.x, tid = threadIdx.x;
    int M = g_selcnt[b]; if (M > SEL_CAP) M = SEL_CAP;
    for (int i = tid; i < M; i += 1024) ssk[i] = g_sel[b*SEL_CAP + i];
    __syncthreads();
    for (int i = tid; i < M; i += 1024) {
        ull v = ssk[i];
        int r = 0;
        for (int j = 0; j < M; j++) r += (ssk[j] > v);
        if (r < NPROP) stop[r] = v;
    }
    __syncthreads();
    // qf: 200 x 128
    for (int e = tid; e < NPROP*CC; e += 1024) {
        int p = e >> 7, c = e & 127;
        unsigned key = 0xFFFFFFFFu - (unsigned)(stop[p] & 0xFFFFFFFFu);
        int cls = key / HW, idx = key - cls*HW;
        int row = g_map[b*HW + idx];
        out[OFF_QF + (b*CC + c)*NPROP + p] =
            feat[(size_t)row*CC + c] + Wcls[c*NCLS + cls] + bcls[c];
    }
    // qhs: 200 x 10
    for (int e = tid; e < NPROP*NCLS; e += 1024) {
        int p = e / NCLS, c = e - p*NCLS;
        unsigned key = 0xFFFFFFFFu - (unsigned)(stop[p] & 0xFFFFFFFFu);
        int cls = key / HW, idx = key - cls*HW;
        int row = g_map[b*HW + idx];
        out[OFF_QHS + (b*NCLS + c)*NPROP + p] = g_supp_pt[row*NCLS + c];
    }
    // pos + cls
    for (int p = tid; p < NPROP; p += 1024) {
        unsigned key = 0xFFFFFFFFu - (unsigned)(stop[p] & 0xFFFFFFFFu);
        int cls = key / HW, idx = key - cls*HW;
        out[OFF_POS + (b*NPROP + p)*2 + 0] = (float)(idx % WG);
        out[OFF_POS + (b*NPROP + p)*2 + 1] = (float)(idx / WG);
        out[OFF_CLS + b*NPROP + p] = (float)cls;
    }
}

// ---------------- launch ----------------------------------------------------
extern "C" void kernel_launch(void* const* d_in, const int* in_sizes, int n_in,
                              void* d_out, int out_size)
{
    const float* feat = (const float*)d_in[0];
    const float* W1   = (const float*)d_in[1];
    const float* b1   = (const float*)d_in[2];
    const float* W2   = (const float*)d_in[3];
    const float* b2   = (const float*)d_in[4];
    const float* Wcls = (const float*)d_in[5];
    const float* bcls = (const float*)d_in[6];
    const int*   idxs = (const int*)d_in[7];
    float* out = (float*)d_out;

    cudaFuncSetAttribute(gemm_kernel, cudaFuncAttributeMaxDynamicSharedMemorySize,
                         SMEM_FLOATS * (int)sizeof(float));

    init_kernel<<<1024, 256>>>();
    gemm_kernel<<<GEMM_GRID, 256, SMEM_FLOATS * sizeof(float)>>>(feat, W1, b1, W2, b2, idxs);
    nms_kernel<<<(NPTS + 255)/256, 256>>>(idxs);
    thresh_kernel<<<BB, 1024>>>();
    gather_kernel<<<(NPTS + 255)/256, 256>>>(idxs);
    finalize_kernel<<<BB, 1024>>>(feat, Wcls, bcls, out);
}

// round 10
// speedup vs baseline: 1.0396x; 1.0396x over previous
#include <cuda_runtime.h>
#include <math.h>

#define BB    2
#define HH    360
#define WG    360
#define HW    (HH*WG)          // 129600
#define NCLS  10
#define NPROP 200
#define CC    128
#define NPTS  80000
#define NBUCK 8192             // bucket = float_bits >> 17
#define SEL_CAP 4096

// output layout: qf (B,C,P) | query_pos (B,P,2) | qhs (B,NCLS,P) | cls (B,P)
#define OFF_QF  0
#define OFF_POS (BB*CC*NPROP)            // 51200
#define OFF_QHS (OFF_POS + BB*NPROP*2)   // 52000
#define OFF_CLS (OFF_QHS + BB*NCLS*NPROP)// 56000

typedef unsigned long long ull;

// ---------------- scratch ---------------------------------------------------
__device__ float g_heat8[BB*HW*8];       // packed: [b*HW+cell][c], classes 0..7
__device__ float g_supp_pt[NPTS*NCLS];   // per-point suppressed heat, all 10 cls
__device__ int   g_map[BB*HW];           // cell -> row; only read at occupied cells
__device__ unsigned g_hist[BB*NBUCK];
__device__ int   g_thr[BB];
__device__ int   g_selcnt[BB];
__device__ ull   g_sel[BB*SEL_CAP];

// ---------------- packed f32x2 helpers --------------------------------------
__device__ __forceinline__ ull pk2(float lo, float hi) {
    ull r;
    asm("mov.b64 %0, {%1, %2};" : "=l"(r)
        : "r"(__float_as_uint(lo)), "r"(__float_as_uint(hi)));
    return r;
}
__device__ __forceinline__ ull pk1(float v) {
    ull r;
    asm("mov.b64 %0, {%1, %1};" : "=l"(r) : "r"(__float_as_uint(v)));
    return r;
}
__device__ __forceinline__ void upk(ull p, float& lo, float& hi) {
    unsigned a, b;
    asm("mov.b64 {%0, %1}, %2;" : "=r"(a), "=r"(b) : "l"(p));
    lo = __uint_as_float(a); hi = __uint_as_float(b);
}
__device__ __forceinline__ ull ffma2(ull a, ull b, ull c) {
    ull d;
    asm("fma.rn.f32x2 %0, %1, %2, %3;" : "=l"(d) : "l"(a), "l"(b), "l"(c));
    return d;
}
__device__ __forceinline__ float sigmf(float x) {
    return 1.f / (1.f + expf(-x));
}

// ---------------- init ------------------------------------------------------
__global__ void init_kernel() {
    int stride = gridDim.x * blockDim.x;
    int i0 = blockIdx.x * blockDim.x + threadIdx.x;
    float4 z = make_float4(0.f, 0.f, 0.f, 0.f);
    for (int j = i0; j < BB*HW*8/4; j += stride) ((float4*)g_heat8)[j] = z;
    uint4 zu = make_uint4(0u, 0u, 0u, 0u);
    for (int j = i0; j < BB*NBUCK/4; j += stride) ((uint4*)g_hist)[j] = zu;
    if (i0 < BB) g_selcnt[i0] = 0;
}

// ---------------- fused MLP head (R6 structure: 625 x 128-row tiles) --------
// block: 256 threads, 128 rows x 128 cols tile; W1 resident in smem.
// dyn smem (floats): [0,16384) W1 | [16384,20608) A(32x132) |
//                    reuse [0,16896) H(128x132) | [20608,21888) W2
#define SMEM_FLOATS 21888
__global__ void __launch_bounds__(256, 2)
gemm_kernel(const float* __restrict__ feat, const float* __restrict__ W1,
            const float* __restrict__ b1,  const float* __restrict__ W2,
            const float* __restrict__ b2,  const int* __restrict__ idxs)
{
    extern __shared__ float sm[];
    float* sW1 = sm;                 // 128*128
    float* sA  = sm + 16384;         // 32*132
    float* sH  = sm;                 // 128*132 (reuses W1+A after phase 1)
    float* sW2 = sm + 20608;         // 128*10

    const int tid = threadIdx.x;
    const int rowBase = blockIdx.x * 128;

    for (int i = tid*4; i < CC*CC; i += 256*4)
        *(float4*)(sW1 + i) = *(const float4*)(W1 + i);
    for (int i = tid; i < CC*NCLS; i += 256)
        sW2[i] = W2[i];

    const int tn = tid & 15, tm = tid >> 4;
    const int c0 = tn*4;          // cols c0..c0+3
    const int c1 = 64 + tn*4;     // cols c1..c1+3

    // acc pairs: [i][0]=(c0,c0+1) [i][1]=(c0+2,c0+3) [i][2]=(c1,c1+1) [i][3]=(c1+2,c1+3)
    ull acc2[8][4];
    {
        ull p0 = pk2(b1[c0],   b1[c0+1]);
        ull p1 = pk2(b1[c0+2], b1[c0+3]);
        ull p2 = pk2(b1[c1],   b1[c1+1]);
        ull p3 = pk2(b1[c1+2], b1[c1+3]);
#pragma unroll
        for (int i = 0; i < 8; i++) {
            acc2[i][0] = p0; acc2[i][1] = p1; acc2[i][2] = p2; acc2[i][3] = p3;
        }
    }
    __syncthreads();   // W1/W2 visible

    const int lrow = tid >> 3;          // 0..31
    const int lk4  = (tid & 7) * 4;     // 0..28
    for (int kc = 0; kc < 4; kc++) {
#pragma unroll
        for (int pass = 0; pass < 4; pass++) {
            int r = lrow + pass*32;
            float4 v = *(const float4*)(feat + (size_t)(rowBase + r)*CC + kc*32 + lk4);
            sA[(lk4+0)*132 + r] = v.x;
            sA[(lk4+1)*132 + r] = v.y;
            sA[(lk4+2)*132 + r] = v.z;
            sA[(lk4+3)*132 + r] = v.w;
        }
        __syncthreads();
#pragma unroll 4
        for (int k = 0; k < 32; k++) {
            float a[8];
            *(float4*)(a)    = *(float4*)(sA + k*132 + tm*8);
            *(float4*)(a+4)  = *(float4*)(sA + k*132 + tm*8 + 4);
            const ull* bw = (const ull*)(sW1 + (kc*32+k)*128);
            ull w0 = bw[tn*2];
            ull w1 = bw[tn*2 + 1];
            ull w2 = bw[32 + tn*2];
            ull w3 = bw[32 + tn*2 + 1];
#pragma unroll
            for (int i = 0; i < 8; i++) {
                ull aa = pk1(a[i]);
                acc2[i][0] = ffma2(aa, w0, acc2[i][0]);
                acc2[i][1] = ffma2(aa, w1, acc2[i][1]);
                acc2[i][2] = ffma2(aa, w2, acc2[i][2]);
                acc2[i][3] = ffma2(aa, w3, acc2[i][3]);
            }
        }
        __syncthreads();
    }

    // relu -> sH (packed 8B stores; offsets even -> aligned)
#pragma unroll
    for (int i = 0; i < 8; i++) {
        int r = tm*8 + i;
        float lo, hi;
        upk(acc2[i][0], lo, hi);
        *(ull*)(sH + r*132 + c0)     = pk2(fmaxf(lo,0.f), fmaxf(hi,0.f));
        upk(acc2[i][1], lo, hi);
        *(ull*)(sH + r*132 + c0 + 2) = pk2(fmaxf(lo,0.f), fmaxf(hi,0.f));
        upk(acc2[i][2], lo, hi);
        *(ull*)(sH + r*132 + c1)     = pk2(fmaxf(lo,0.f), fmaxf(hi,0.f));
        upk(acc2[i][3], lo, hi);
        *(ull*)(sH + r*132 + c1 + 2) = pk2(fmaxf(lo,0.f), fmaxf(hi,0.f));
    }
    __syncthreads();

    // phase 2: hm = H @ W2 + b2, sigmoid, scatter (packed heat8 layout)
    const int r   = tid & 127;
    const int grp = tid >> 7;      // 0 -> cls 0..4, 1 -> cls 5..9
    float o[5];
#pragma unroll
    for (int i = 0; i < 5; i++) o[i] = b2[grp*5 + i];
    for (int j = 0; j < 128; j++) {
        float a = sH[r*132 + j];
#pragma unroll
        for (int i = 0; i < 5; i++)
            o[i] = fmaf(a, sW2[j*NCLS + grp*5 + i], o[i]);
    }
    const int gr = rowBase + r;
    const int bi = idxs[gr*3], yi = idxs[gr*3+1], xi = idxs[gr*3+2];
    const int cell = bi*HW + yi*WG + xi;
    if (grp == 0) {
#pragma unroll
        for (int i = 0; i < 5; i++)
            g_heat8[(size_t)cell*8 + i] = sigmf(o[i]);
        g_map[cell] = gr;
    } else {
#pragma unroll
        for (int i = 0; i < 3; i++)                 // classes 5,6,7
            g_heat8[(size_t)cell*8 + 5 + i] = sigmf(o[i]);
#pragma unroll
        for (int i = 3; i < 5; i++) {               // classes 8,9: NMS bypass
            float s = sigmf(o[i]);
            g_supp_pt[gr*NCLS + 5 + i] = s;
            atomicAdd(&g_hist[bi*NBUCK + (__float_as_uint(s) >> 17)], 1u);
        }
    }
}

// ---------------- NMS per point (packed heat, classes 0..7) -----------------
__global__ void nms_kernel(const int* __restrict__ idxs) {
    int t = blockIdx.x * 256 + threadIdx.x;
    if (t >= NPTS) return;
    int b = idxs[3*t], y = idxs[3*t+1], x = idxs[3*t+2];
    int cell = b*HW + y*WG + x;
    float s[8];
    if (y > 0 && y < HH-1 && x > 0 && x < WG-1) {
        const float4* cp = (const float4*)(g_heat8 + (size_t)cell*8);
        float4 cv0 = cp[0], cv1 = cp[1];
        float ctr[8] = {cv0.x, cv0.y, cv0.z, cv0.w, cv1.x, cv1.y, cv1.z, cv1.w};
        float nmx[8] = {0.f,0.f,0.f,0.f,0.f,0.f,0.f,0.f};
        const int offs[8] = {-WG-1, -WG, -WG+1, -1, 1, WG-1, WG, WG+1};
#pragma unroll
        for (int n = 0; n < 8; n++) {
            const float4* q = (const float4*)(g_heat8 + (size_t)(cell + offs[n])*8);
            float4 u0 = q[0], u1 = q[1];
            nmx[0] = fmaxf(nmx[0], u0.x); nmx[1] = fmaxf(nmx[1], u0.y);
            nmx[2] = fmaxf(nmx[2], u0.z); nmx[3] = fmaxf(nmx[3], u0.w);
            nmx[4] = fmaxf(nmx[4], u1.x); nmx[5] = fmaxf(nmx[5], u1.y);
            nmx[6] = fmaxf(nmx[6], u1.z); nmx[7] = fmaxf(nmx[7], u1.w);
        }
#pragma unroll
        for (int c = 0; c < 8; c++)
            s[c] = (ctr[c] >= nmx[c]) ? ctr[c] : 0.f;
    } else {
#pragma unroll
        for (int c = 0; c < 8; c++) s[c] = 0.f;   // border suppressed (cls 0..7)
    }
#pragma unroll
    for (int c = 0; c < 8; c++) {
        g_supp_pt[t*NCLS + c] = s[c];
        if (s[c] > 0.f)
            atomicAdd(&g_hist[b*NBUCK + (__float_as_uint(s[c]) >> 17)], 1u);
    }
}

// ---------------- threshold bucket of rank-200 (warp-shuffle suffix scan) ---
__global__ void thresh_kernel() {
    __shared__ unsigned wtot[32], wexc[32];
    int b = blockIdx.x;
    const unsigned* h = g_hist + b*NBUCK;
    int t = threadIdx.x;
    uint4 h0 = ((const uint4*)h)[t*2];
    uint4 h1 = ((const uint4*)h)[t*2 + 1];
    unsigned hv[8] = {h0.x, h0.y, h0.z, h0.w, h1.x, h1.y, h1.z, h1.w};
    unsigned v = hv[0]+hv[1]+hv[2]+hv[3]+hv[4]+hv[5]+hv[6]+hv[7];

    int lane = t & 31, wid = t >> 5;
    unsigned s = v;                              // inclusive lane-suffix
#pragma unroll
    for (int off = 1; off < 32; off <<= 1) {
        unsigned u = __shfl_down_sync(0xFFFFFFFFu, s, off);
        if (lane + off < 32) s += u;
    }
    if (lane == 0) wtot[wid] = s;
    __syncthreads();
    if (wid == 0) {
        unsigned ws = wtot[lane];
        unsigned sw = ws;
#pragma unroll
        for (int off = 1; off < 32; off <<= 1) {
            unsigned u = __shfl_down_sync(0xFFFFFFFFu, sw, off);
            if (lane + off < 32) sw += u;
        }
        wexc[lane] = sw - ws;                    // strict suffix of warp totals
    }
    __syncthreads();
    unsigned S = s + wexc[wid];                  // suffix over all t' >= t
    unsigned Snext = S - v;
    if (S >= NPROP && Snext < NPROP) {
        unsigned acc = Snext;
        int T = t*8;
        for (int i = 7; i >= 0; i--) {
            if (acc + hv[i] >= NPROP) { T = t*8 + i; break; }
            acc += hv[i];
        }
        g_thr[b] = T;
    }
}

// ---------------- gather candidates >= threshold (per point) ----------------
__global__ void gather_kernel(const int* __restrict__ idxs) {
    int t = blockIdx.x * 256 + threadIdx.x;
    if (t >= NPTS) return;
    int b = idxs[3*t], y = idxs[3*t+1], x = idxs[3*t+2];
    int cell = y*WG + x;
    int T = g_thr[b];
#pragma unroll
    for (int c = 0; c < NCLS; c++) {
        float sv = g_supp_pt[t*NCLS + c];
        unsigned vb = __float_as_uint(sv);
        if (sv > 0.f && (int)(vb >> 17) >= T) {
            unsigned j = (unsigned)(c*HW + cell);
            ull sk = ((ull)vb << 32) | (ull)(0xFFFFFFFFu - j);
            int p = atomicAdd(&g_selcnt[b], 1);
            if (p < SEL_CAP) g_sel[b*SEL_CAP + p] = sk;
        }
    }
}

// ---------------- finalize: exact rank + all outputs (1 block / batch) ------
__global__ void finalize_kernel(const float* __restrict__ feat,
                                const float* __restrict__ Wcls,
                                const float* __restrict__ bcls,
                                float* __restrict__ out)
{
    __shared__ ull ssk[SEL_CAP];
    __shared__ ull stop[NPROP];
    int b = blockIdx.x, tid = threadIdx.x;
    int M = g_selcnt[b]; if (M > SEL_CAP) M = SEL_CAP;
    for (int i = tid; i < M; i += 1024) ssk[i] = g_sel[b*SEL_CAP + i];
    __syncthreads();
    for (int i = tid; i < M; i += 1024) {
        ull v = ssk[i];
        int r = 0;
        for (int j = 0; j < M; j++) r += (ssk[j] > v);
        if (r < NPROP) stop[r] = v;
    }
    __syncthreads();
    // qf: 200 x 128
    for (int e = tid; e < NPROP*CC; e += 1024) {
        int p = e >> 7, c = e & 127;
        unsigned key = 0xFFFFFFFFu - (unsigned)(stop[p] & 0xFFFFFFFFu);
        int cls = key / HW, idx = key - cls*HW;
        int row = g_map[b*HW + idx];
        out[OFF_QF + (b*CC + c)*NPROP + p] =
            feat[(size_t)row*CC + c] + Wcls[c*NCLS + cls] + bcls[c];
    }
    // qhs: 200 x 10
    for (int e = tid; e < NPROP*NCLS; e += 1024) {
        int p = e / NCLS, c = e - p*NCLS;
        unsigned key = 0xFFFFFFFFu - (unsigned)(stop[p] & 0xFFFFFFFFu);
        int cls = key / HW, idx = key - cls*HW;
        int row = g_map[b*HW + idx];
        out[OFF_QHS + (b*NCLS + c)*NPROP + p] = g_supp_pt[row*NCLS + c];
    }
    // pos + cls
    for (int p = tid; p < NPROP; p += 1024) {
        unsigned key = 0xFFFFFFFFu - (unsigned)(stop[p] & 0xFFFFFFFFu);
        int cls = key / HW, idx = key - cls*HW;
        out[OFF_POS + (b*NPROP + p)*2 + 0] = (float)(idx % WG);
        out[OFF_POS + (b*NPROP + p)*2 + 1] = (float)(idx / WG);
        out[OFF_CLS + b*NPROP + p] = (float)cls;
    }
}

// ---------------- launch ----------------------------------------------------
extern "C" void kernel_launch(void* const* d_in, const int* in_sizes, int n_in,
                              void* d_out, int out_size)
{
    const float* feat = (const float*)d_in[0];
    const float* W1   = (const float*)d_in[1];
    const float* b1   = (const float*)d_in[2];
    const float* W2   = (const float*)d_in[3];
    const float* b2   = (const float*)d_in[4];
    const float* Wcls = (const float*)d_in[5];
    const float* bcls = (const float*)d_in[6];
    const int*   idxs = (const int*)d_in[7];
    float* out = (float*)d_out;

    cudaFuncSetAttribute(gemm_kernel, cudaFuncAttributeMaxDynamicSharedMemorySize,
                         SMEM_FLOATS * (int)sizeof(float));

    init_kernel<<<1024, 256>>>();
    gemm_kernel<<<NPTS/128, 256, SMEM_FLOATS * sizeof(float)>>>(feat, W1, b1, W2, b2, idxs);
    nms_kernel<<<(NPTS + 255)/256, 256>>>(idxs);
    thresh_kernel<<<BB, 1024>>>();
    gather_kernel<<<(NPTS + 255)/256, 256>>>(idxs);
    finalize_kernel<<<BB, 1024>>>(feat, Wcls, bcls, out);
}